// round 2
// baseline (speedup 1.0000x reference)
#include <cuda_runtime.h>
#include <cstdint>

#define NMAX 50000
#define EMAX 800000
#define DIM 128

// -------- scratch (device globals; no allocation allowed) --------
__device__ float g_agg[(size_t)NMAX * DIM];   // aggregation buffer (reused)
__device__ float g_x1[(size_t)NMAX * DIM];    // layer-1 activations
__device__ float g_Wt1[256 * 128];            // [k][n] transposed concat weights, layer 1
__device__ float g_Wt23[256 * 256];           // [k][n] transposed concat weights, layers 2+3
__device__ float g_b1[128];
__device__ float g_b23[256];
__device__ int   g_deg[NMAX];
__device__ int   g_rowptr[NMAX + 1];
__device__ int   g_cursor[NMAX];
__device__ int   g_col[EMAX];
__device__ int   g_is64;

// -------- edge-index dtype detection (int64 vs int32) --------
__global__ void detect_kernel(const unsigned long long* ei) {
    // Values are in [0, 50000). If data is int64, every hi 32-bit word is 0.
    // If data is int32, the hi word of slot i is edge[2i+1] (random, ~never all 0).
    int ok = 1;
    for (int i = 0; i < 128; i++) {
        if ((ei[i] >> 32) != 0ULL) { ok = 0; break; }
    }
    g_is64 = ok;
}

__device__ __forceinline__ int edge_at(const void* ei, long long idx) {
    if (g_is64) return (int)((const long long*)ei)[idx];
    return ((const int*)ei)[idx];
}

// -------- CSR build --------
__global__ void zero_deg_kernel(int n) {
    int i = blockIdx.x * blockDim.x + threadIdx.x;
    if (i < n) g_deg[i] = 0;
}

__global__ void count_kernel(const void* ei, int e) {
    int i = blockIdx.x * blockDim.x + threadIdx.x;
    if (i >= e) return;
    int dst = edge_at(ei, (long long)e + i);
    atomicAdd(&g_deg[dst], 1);
}

__global__ void scan_kernel(int n) {
    // single-block exclusive scan of g_deg -> g_rowptr (+ g_cursor copy)
    __shared__ int s[1024];
    int tid = threadIdx.x;
    int running = 0;
    for (int base = 0; base < n; base += 1024) {
        int i = base + tid;
        int v = (i < n) ? g_deg[i] : 0;
        s[tid] = v;
        __syncthreads();
        for (int off = 1; off < 1024; off <<= 1) {
            int t = (tid >= off) ? s[tid - off] : 0;
            __syncthreads();
            s[tid] += t;
            __syncthreads();
        }
        int total = s[1023];
        int excl = s[tid] - v + running;
        if (i < n) { g_rowptr[i] = excl; g_cursor[i] = excl; }
        running += total;
        __syncthreads();
    }
    if (tid == 0) g_rowptr[n] = running;
}

__global__ void scatter_kernel(const void* ei, int e) {
    int i = blockIdx.x * blockDim.x + threadIdx.x;
    if (i >= e) return;
    int src = edge_at(ei, i);
    int dst = edge_at(ei, (long long)e + i);
    int pos = atomicAdd(&g_cursor[dst], 1);
    g_col[pos] = src;
}

// -------- weight prep: transpose + concat into [K=256][Nout] layout --------
__global__ void prep_kernel(const float* __restrict__ W1l, const float* __restrict__ b1l,
                            const float* __restrict__ W1r,
                            const float* __restrict__ W2l, const float* __restrict__ b2l,
                            const float* __restrict__ W2r,
                            const float* __restrict__ W3l, const float* __restrict__ b3l,
                            const float* __restrict__ W3r) {
    int i = blockIdx.x * blockDim.x + threadIdx.x;
    if (i < 32768) {                       // Wt1: [256][128]
        int k = i >> 7, nn = i & 127;
        g_Wt1[i] = (k < 128) ? W1l[nn * 128 + k] : W1r[nn * 128 + (k - 128)];
    } else if (i < 32768 + 65536) {        // Wt23: [256][256]
        int t = i - 32768;
        int k = t >> 8, nn = t & 255;
        const float* W = (nn < 128) ? ((k < 128) ? W2l : W2r)
                                    : ((k < 128) ? W3l : W3r);
        g_Wt23[t] = W[(nn & 127) * 128 + (k & 127)];
    } else if (i < 98304 + 128) {          // bias layer 1
        int t = i - 98304;
        g_b1[t] = b1l[t];
    } else if (i < 98432 + 256) {          // bias layers 2+3
        int t = i - 98432;
        g_b23[t] = (t < 128) ? b2l[t] : b3l[t - 128];
    }
}

// -------- mean aggregation: warp per node, no float atomics --------
__global__ void agg_kernel(const float* __restrict__ X, float* __restrict__ out, int n) {
    int warp = (blockIdx.x * blockDim.x + threadIdx.x) >> 5;
    int lane = threadIdx.x & 31;
    if (warp >= n) return;
    int s = g_rowptr[warp], e2 = g_rowptr[warp + 1];
    float4 acc = make_float4(0.f, 0.f, 0.f, 0.f);
    int j = s;
    for (; j + 1 < e2; j += 2) {
        int c0 = g_col[j], c1 = g_col[j + 1];
        float4 v0 = *(const float4*)(X + (size_t)c0 * DIM + lane * 4);
        float4 v1 = *(const float4*)(X + (size_t)c1 * DIM + lane * 4);
        acc.x += v0.x + v1.x; acc.y += v0.y + v1.y;
        acc.z += v0.z + v1.z; acc.w += v0.w + v1.w;
    }
    if (j < e2) {
        int c0 = g_col[j];
        float4 v0 = *(const float4*)(X + (size_t)c0 * DIM + lane * 4);
        acc.x += v0.x; acc.y += v0.y; acc.z += v0.z; acc.w += v0.w;
    }
    int cnt = e2 - s;
    float inv = 1.0f / (float)(cnt > 0 ? cnt : 1);
    float4 r = make_float4(acc.x * inv, acc.y * inv, acc.z * inv, acc.w * inv);
    *(float4*)(out + (size_t)warp * DIM + lane * 4) = r;
}

// -------- fused SAGE GEMM: C = [A0|A1] @ Wt + bias (K=256) --------
// NT = total output cols (128 or 256). Cols [0,128) -> C0, [128,256) -> C1.
template <int NT, bool RELU>
__global__ void __launch_bounds__(256, 2)
gemm_kernel(const float* __restrict__ A0, const float* __restrict__ A1,
            const float* __restrict__ B, const float* __restrict__ bias,
            float* __restrict__ C0, float* __restrict__ C1, int M) {
    __shared__ float As[16][128];
    __shared__ float Bs[16][128];
    int tid = threadIdx.x;
    int tx = tid & 15, ty = tid >> 4;
    int m0 = blockIdx.y * 128;
    int n0 = blockIdx.x * 128;

    float acc[8][8];
#pragma unroll
    for (int i = 0; i < 8; i++)
#pragma unroll
        for (int j = 0; j < 8; j++) acc[i][j] = 0.f;

    int lrow = tid >> 1;           // 0..127
    int lk = (tid & 1) * 8;        // 0 or 8
    int brow = tid >> 4;           // 0..15
    int bn = (tid & 15) * 8;       // 0..120
    bool arow_ok = (m0 + lrow) < M;

    for (int kc = 0; kc < 16; kc++) {
        const float* Asrc = (kc < 8) ? A0 : A1;
        int koff = (kc & 7) * 16;

        float4 av0, av1;
        if (arow_ok) {
            const float* p = Asrc + (size_t)(m0 + lrow) * 128 + koff + lk;
            av0 = *(const float4*)p;
            av1 = *(const float4*)(p + 4);
        } else {
            av0 = make_float4(0.f, 0.f, 0.f, 0.f);
            av1 = av0;
        }
        const float* bp = B + (size_t)(kc * 16 + brow) * NT + n0 + bn;
        float4 bv0 = *(const float4*)bp;
        float4 bv1 = *(const float4*)(bp + 4);

        __syncthreads();
        As[lk + 0][lrow] = av0.x; As[lk + 1][lrow] = av0.y;
        As[lk + 2][lrow] = av0.z; As[lk + 3][lrow] = av0.w;
        As[lk + 4][lrow] = av1.x; As[lk + 5][lrow] = av1.y;
        As[lk + 6][lrow] = av1.z; As[lk + 7][lrow] = av1.w;
        *(float4*)&Bs[brow][bn] = bv0;
        *(float4*)&Bs[brow][bn + 4] = bv1;
        __syncthreads();

#pragma unroll
        for (int kk = 0; kk < 16; kk++) {
            float a[8], b[8];
            *(float4*)(a) = *(const float4*)&As[kk][ty * 8];
            *(float4*)(a + 4) = *(const float4*)&As[kk][ty * 8 + 4];
            *(float4*)(b) = *(const float4*)&Bs[kk][tx * 8];
            *(float4*)(b + 4) = *(const float4*)&Bs[kk][tx * 8 + 4];
#pragma unroll
            for (int i = 0; i < 8; i++)
#pragma unroll
                for (int j = 0; j < 8; j++) acc[i][j] += a[i] * b[j];
        }
    }

    float* Cdst = (NT == 128 || n0 == 0) ? C0 : C1;
#pragma unroll
    for (int i = 0; i < 8; i++) {
        int row = m0 + ty * 8 + i;
        if (row < M) {
            float4 o0, o1;
            float v[8];
#pragma unroll
            for (int j = 0; j < 8; j++) {
                float t = acc[i][j] + bias[n0 + tx * 8 + j];
                if (RELU) t = fmaxf(t, 0.f);
                v[j] = t;
            }
            o0 = make_float4(v[0], v[1], v[2], v[3]);
            o1 = make_float4(v[4], v[5], v[6], v[7]);
            float* cp = Cdst + (size_t)row * 128 + tx * 8;
            *(float4*)cp = o0;
            *(float4*)(cp + 4) = o1;
        }
    }
}

extern "C" void kernel_launch(void* const* d_in, const int* in_sizes, int n_in,
                              void* d_out, int out_size) {
    const float* x   = (const float*)d_in[0];
    const void*  ei  = d_in[1];
    const float* W1l = (const float*)d_in[2];
    const float* b1l = (const float*)d_in[3];
    const float* W1r = (const float*)d_in[4];
    const float* W2l = (const float*)d_in[5];
    const float* b2l = (const float*)d_in[6];
    const float* W2r = (const float*)d_in[7];
    const float* W3l = (const float*)d_in[8];
    const float* b3l = (const float*)d_in[9];
    const float* W3r = (const float*)d_in[10];

    int n = in_sizes[0] / DIM;   // 50000
    int e = in_sizes[1] / 2;     // 800000

    float* out0 = (float*)d_out;                     // h_ (layer 2)
    float* out1 = out0 + (size_t)n * DIM;            // h  (layer 3)

    float *agg, *x1, *Wt1, *Wt23, *b1, *b23;
    cudaGetSymbolAddress((void**)&agg,  g_agg);
    cudaGetSymbolAddress((void**)&x1,   g_x1);
    cudaGetSymbolAddress((void**)&Wt1,  g_Wt1);
    cudaGetSymbolAddress((void**)&Wt23, g_Wt23);
    cudaGetSymbolAddress((void**)&b1,   g_b1);
    cudaGetSymbolAddress((void**)&b23,  g_b23);

    int eblocks = (e + 255) / 256;
    int nblocks = (n + 255) / 256;
    int mtiles = (n + 127) / 128;

    // CSR build
    detect_kernel<<<1, 1>>>((const unsigned long long*)ei);
    zero_deg_kernel<<<nblocks, 256>>>(n);
    count_kernel<<<eblocks, 256>>>(ei, e);
    scan_kernel<<<1, 1024>>>(n);
    scatter_kernel<<<eblocks, 256>>>(ei, e);

    // Weight transpose/concat
    prep_kernel<<<(98688 + 255) / 256, 256>>>(W1l, b1l, W1r, W2l, b2l, W2r, W3l, b3l, W3r);

    // Layer 1: agg1 = mean-agg(x); x1 = relu([agg1|x] @ Wt1 + b1)
    agg_kernel<<<(n + 7) / 8, 256>>>(x, agg, n);
    gemm_kernel<128, true><<<dim3(1, mtiles), 256>>>(agg, x, Wt1, b1, x1, nullptr, n);

    // Layers 2+3 (shared aggregation): agg2 = mean-agg(x1)
    agg_kernel<<<(n + 7) / 8, 256>>>(x1, agg, n);
    // [h_ | h] = [agg2|x1] @ Wt23 + b23
    gemm_kernel<256, false><<<dim3(2, mtiles), 256>>>(agg, x1, Wt23, b23, out0, out1, n);
}

// round 3
// speedup vs baseline: 1.1785x; 1.1785x over previous
#include <cuda_runtime.h>
#include <cstdint>

#define NMAX 50000
#define EMAX 800000
#define DIM 128
#define SCAN_BLOCKS 196   // ceil(50000/256)

// -------- scratch (device globals; no allocation allowed) --------
__device__ float g_agg[(size_t)NMAX * DIM];   // aggregation buffer (reused)
__device__ float g_x1[(size_t)NMAX * DIM];    // layer-1 activations
__device__ float g_Wt1[256 * 128];            // [k][n] transposed concat weights, layer 1
__device__ float g_Wt23[256 * 256];           // [k][n] transposed concat weights, layers 2+3
__device__ float g_b1[128];
__device__ float g_b23[256];
__device__ int   g_deg[NMAX];
__device__ int   g_rowptr[NMAX + 1];
__device__ int   g_cursor[NMAX];
__device__ int   g_col[EMAX];
__device__ int   g_bsum[SCAN_BLOCKS];
__device__ int   g_boff[SCAN_BLOCKS + 1];
__device__ int   g_is64;

// -------- edge-index dtype detection (int64 vs int32), parallel, no early exit --------
__global__ void detect_kernel(const unsigned long long* ei) {
    int lane = threadIdx.x;
    unsigned long long hi = 0;
    #pragma unroll
    for (int k = 0; k < 4; k++) hi |= (ei[lane + 32 * k] >> 32);
    unsigned any = __ballot_sync(0xFFFFFFFFu, hi != 0ULL);
    if (lane == 0) g_is64 = (any == 0u);
}

__device__ __forceinline__ int edge_at(const void* ei, long long idx) {
    if (g_is64) return (int)((const long long*)ei)[idx];
    return ((const int*)ei)[idx];
}

// -------- CSR build --------
__global__ void zero_deg_kernel(int n) {
    int i = blockIdx.x * blockDim.x + threadIdx.x;
    if (i < n) g_deg[i] = 0;
}

__global__ void count_kernel(const void* ei, int e) {
    int i = blockIdx.x * blockDim.x + threadIdx.x;
    if (i >= e) return;
    int dst = edge_at(ei, (long long)e + i);
    atomicAdd(&g_deg[dst], 1);
}

__device__ __forceinline__ int warp_incl_scan(int v, int lane) {
    #pragma unroll
    for (int o = 1; o < 32; o <<= 1) {
        int t = __shfl_up_sync(0xFFFFFFFFu, v, o);
        if (lane >= o) v += t;
    }
    return v;
}

// block-level exclusive scan of 256 values; returns (excl, block_total via smem)
__device__ __forceinline__ int block_scan256(int v, int tid, int* block_total) {
    __shared__ int wsum[8];
    int lane = tid & 31, wid = tid >> 5;
    int incl = warp_incl_scan(v, lane);
    if (lane == 31) wsum[wid] = incl;
    __syncthreads();
    if (wid == 0) {
        int s = (lane < 8) ? wsum[lane] : 0;
        s = warp_incl_scan(s, lane);
        if (lane < 8) wsum[lane] = s;
    }
    __syncthreads();
    int off = (wid > 0) ? wsum[wid - 1] : 0;
    *block_total = wsum[7];
    return off + incl - v;
}

// scan phase 1: per-block exclusive scan of degrees
__global__ void scan1_kernel(int n) {
    int tid = threadIdx.x;
    int i = blockIdx.x * 256 + tid;
    int v = (i < n) ? g_deg[i] : 0;
    int total;
    int excl = block_scan256(v, tid, &total);
    if (i < n) g_rowptr[i] = excl;
    if (tid == 0) g_bsum[blockIdx.x] = total;
}

// scan phase 2: exclusive scan of block sums (single block, 256 >= SCAN_BLOCKS)
__global__ void scan2_kernel() {
    int tid = threadIdx.x;
    int v = (tid < SCAN_BLOCKS) ? g_bsum[tid] : 0;
    int total;
    int excl = block_scan256(v, tid, &total);
    if (tid < SCAN_BLOCKS) g_boff[tid] = excl;
    if (tid == 0) g_boff[SCAN_BLOCKS] = total;
}

// scan phase 3: add block offsets, init cursor, write rowptr[n]
__global__ void scan3_kernel(int n) {
    int i = blockIdx.x * blockDim.x + threadIdx.x;
    if (i < n) {
        int r = g_rowptr[i] + g_boff[i >> 8];
        g_rowptr[i] = r;
        g_cursor[i] = r;
    }
    if (i == 0) g_rowptr[n] = g_boff[SCAN_BLOCKS];
}

__global__ void scatter_kernel(const void* ei, int e) {
    int i = blockIdx.x * blockDim.x + threadIdx.x;
    if (i >= e) return;
    int src = edge_at(ei, i);
    int dst = edge_at(ei, (long long)e + i);
    int pos = atomicAdd(&g_cursor[dst], 1);
    g_col[pos] = src;
}

// -------- weight prep: transpose + concat into [K=256][Nout] layout --------
__global__ void prep_kernel(const float* __restrict__ W1l, const float* __restrict__ b1l,
                            const float* __restrict__ W1r,
                            const float* __restrict__ W2l, const float* __restrict__ b2l,
                            const float* __restrict__ W2r,
                            const float* __restrict__ W3l, const float* __restrict__ b3l,
                            const float* __restrict__ W3r) {
    int i = blockIdx.x * blockDim.x + threadIdx.x;
    if (i < 32768) {                       // Wt1: [256][128]
        int k = i >> 7, nn = i & 127;
        g_Wt1[i] = (k < 128) ? W1l[nn * 128 + k] : W1r[nn * 128 + (k - 128)];
    } else if (i < 32768 + 65536) {        // Wt23: [256][256]
        int t = i - 32768;
        int k = t >> 8, nn = t & 255;
        const float* W = (nn < 128) ? ((k < 128) ? W2l : W2r)
                                    : ((k < 128) ? W3l : W3r);
        g_Wt23[t] = W[(nn & 127) * 128 + (k & 127)];
    } else if (i < 98304 + 128) {          // bias layer 1
        int t = i - 98304;
        g_b1[t] = b1l[t];
    } else if (i < 98432 + 256) {          // bias layers 2+3
        int t = i - 98432;
        g_b23[t] = (t < 128) ? b2l[t] : b3l[t - 128];
    }
}

// -------- mean aggregation: warp per node, no float atomics --------
__global__ void agg_kernel(const float* __restrict__ X, float* __restrict__ out, int n) {
    int warp = (blockIdx.x * blockDim.x + threadIdx.x) >> 5;
    int lane = threadIdx.x & 31;
    if (warp >= n) return;
    int s = g_rowptr[warp], e2 = g_rowptr[warp + 1];
    float4 acc = make_float4(0.f, 0.f, 0.f, 0.f);
    int j = s;
    for (; j + 1 < e2; j += 2) {
        int c0 = g_col[j], c1 = g_col[j + 1];
        float4 v0 = *(const float4*)(X + (size_t)c0 * DIM + lane * 4);
        float4 v1 = *(const float4*)(X + (size_t)c1 * DIM + lane * 4);
        acc.x += v0.x + v1.x; acc.y += v0.y + v1.y;
        acc.z += v0.z + v1.z; acc.w += v0.w + v1.w;
    }
    if (j < e2) {
        int c0 = g_col[j];
        float4 v0 = *(const float4*)(X + (size_t)c0 * DIM + lane * 4);
        acc.x += v0.x; acc.y += v0.y; acc.z += v0.z; acc.w += v0.w;
    }
    int cnt = e2 - s;
    float inv = 1.0f / (float)(cnt > 0 ? cnt : 1);
    float4 r = make_float4(acc.x * inv, acc.y * inv, acc.z * inv, acc.w * inv);
    *(float4*)(out + (size_t)warp * DIM + lane * 4) = r;
}

// -------- fused SAGE GEMM: C = [A0|A1] @ Wt + bias (K=256) --------
// NT = total output cols (128 or 256). Cols [0,128) -> C0, [128,256) -> C1.
template <int NT, bool RELU>
__global__ void __launch_bounds__(256, 2)
gemm_kernel(const float* __restrict__ A0, const float* __restrict__ A1,
            const float* __restrict__ B, const float* __restrict__ bias,
            float* __restrict__ C0, float* __restrict__ C1, int M) {
    __shared__ float As[16][128];
    __shared__ float Bs[16][128];
    int tid = threadIdx.x;
    int tx = tid & 15, ty = tid >> 4;
    int m0 = blockIdx.y * 128;
    int n0 = blockIdx.x * 128;

    float acc[8][8];
#pragma unroll
    for (int i = 0; i < 8; i++)
#pragma unroll
        for (int j = 0; j < 8; j++) acc[i][j] = 0.f;

    int lrow = tid >> 1;           // 0..127
    int lk = (tid & 1) * 8;        // 0 or 8
    int brow = tid >> 4;           // 0..15
    int bn = (tid & 15) * 8;       // 0..120
    bool arow_ok = (m0 + lrow) < M;

    for (int kc = 0; kc < 16; kc++) {
        const float* Asrc = (kc < 8) ? A0 : A1;
        int koff = (kc & 7) * 16;

        float4 av0, av1;
        if (arow_ok) {
            const float* p = Asrc + (size_t)(m0 + lrow) * 128 + koff + lk;
            av0 = *(const float4*)p;
            av1 = *(const float4*)(p + 4);
        } else {
            av0 = make_float4(0.f, 0.f, 0.f, 0.f);
            av1 = av0;
        }
        const float* bp = B + (size_t)(kc * 16 + brow) * NT + n0 + bn;
        float4 bv0 = *(const float4*)bp;
        float4 bv1 = *(const float4*)(bp + 4);

        __syncthreads();
        As[lk + 0][lrow] = av0.x; As[lk + 1][lrow] = av0.y;
        As[lk + 2][lrow] = av0.z; As[lk + 3][lrow] = av0.w;
        As[lk + 4][lrow] = av1.x; As[lk + 5][lrow] = av1.y;
        As[lk + 6][lrow] = av1.z; As[lk + 7][lrow] = av1.w;
        *(float4*)&Bs[brow][bn] = bv0;
        *(float4*)&Bs[brow][bn + 4] = bv1;
        __syncthreads();

#pragma unroll
        for (int kk = 0; kk < 16; kk++) {
            float a[8], b[8];
            *(float4*)(a) = *(const float4*)&As[kk][ty * 8];
            *(float4*)(a + 4) = *(const float4*)&As[kk][ty * 8 + 4];
            *(float4*)(b) = *(const float4*)&Bs[kk][tx * 8];
            *(float4*)(b + 4) = *(const float4*)&Bs[kk][tx * 8 + 4];
#pragma unroll
            for (int i = 0; i < 8; i++)
#pragma unroll
                for (int j = 0; j < 8; j++) acc[i][j] += a[i] * b[j];
        }
    }

    float* Cdst = (NT == 128 || n0 == 0) ? C0 : C1;
#pragma unroll
    for (int i = 0; i < 8; i++) {
        int row = m0 + ty * 8 + i;
        if (row < M) {
            float4 o0, o1;
            float v[8];
#pragma unroll
            for (int j = 0; j < 8; j++) {
                float t = acc[i][j] + bias[n0 + tx * 8 + j];
                if (RELU) t = fmaxf(t, 0.f);
                v[j] = t;
            }
            o0 = make_float4(v[0], v[1], v[2], v[3]);
            o1 = make_float4(v[4], v[5], v[6], v[7]);
            float* cp = Cdst + (size_t)row * 128 + tx * 8;
            *(float4*)cp = o0;
            *(float4*)(cp + 4) = o1;
        }
    }
}

extern "C" void kernel_launch(void* const* d_in, const int* in_sizes, int n_in,
                              void* d_out, int out_size) {
    const float* x   = (const float*)d_in[0];
    const void*  ei  = d_in[1];
    const float* W1l = (const float*)d_in[2];
    const float* b1l = (const float*)d_in[3];
    const float* W1r = (const float*)d_in[4];
    const float* W2l = (const float*)d_in[5];
    const float* b2l = (const float*)d_in[6];
    const float* W2r = (const float*)d_in[7];
    const float* W3l = (const float*)d_in[8];
    const float* b3l = (const float*)d_in[9];
    const float* W3r = (const float*)d_in[10];

    int n = in_sizes[0] / DIM;   // 50000
    int e = in_sizes[1] / 2;     // 800000

    float* out0 = (float*)d_out;                     // h_ (layer 2)
    float* out1 = out0 + (size_t)n * DIM;            // h  (layer 3)

    float *agg, *x1, *Wt1, *Wt23, *b1, *b23;
    cudaGetSymbolAddress((void**)&agg,  g_agg);
    cudaGetSymbolAddress((void**)&x1,   g_x1);
    cudaGetSymbolAddress((void**)&Wt1,  g_Wt1);
    cudaGetSymbolAddress((void**)&Wt23, g_Wt23);
    cudaGetSymbolAddress((void**)&b1,   g_b1);
    cudaGetSymbolAddress((void**)&b23,  g_b23);

    int eblocks = (e + 255) / 256;
    int nblocks = (n + 255) / 256;
    int mtiles = (n + 127) / 128;

    // CSR build
    detect_kernel<<<1, 32>>>((const unsigned long long*)ei);
    zero_deg_kernel<<<nblocks, 256>>>(n);
    count_kernel<<<eblocks, 256>>>(ei, e);
    scan1_kernel<<<SCAN_BLOCKS, 256>>>(n);
    scan2_kernel<<<1, 256>>>();
    scan3_kernel<<<nblocks, 256>>>(n);
    scatter_kernel<<<eblocks, 256>>>(ei, e);

    // Weight transpose/concat
    prep_kernel<<<(98688 + 255) / 256, 256>>>(W1l, b1l, W1r, W2l, b2l, W2r, W3l, b3l, W3r);

    // Layer 1: agg1 = mean-agg(x); x1 = relu([agg1|x] @ Wt1 + b1)
    agg_kernel<<<(n + 7) / 8, 256>>>(x, agg, n);
    gemm_kernel<128, true><<<dim3(1, mtiles), 256>>>(agg, x, Wt1, b1, x1, nullptr, n);

    // Layers 2+3 (shared aggregation): agg2 = mean-agg(x1)
    agg_kernel<<<(n + 7) / 8, 256>>>(x1, agg, n);
    // [h_ | h] = [agg2|x1] @ Wt23 + b23
    gemm_kernel<256, false><<<dim3(2, mtiles), 256>>>(agg, x1, Wt23, b23, out0, out1, n);
}

// round 5
// speedup vs baseline: 1.9036x; 1.6153x over previous
#include <cuda_runtime.h>
#include <cuda_bf16.h>
#include <cstdint>

#define NMAX 50000
#define EMAX 800000
#define DIM 128
#define SCAN_BLOCKS 196   // ceil(50000/256)

// ---------------- scratch (device globals; no allocation allowed) ----------------
__device__ __nv_bfloat16 g_Ahi[(size_t)NMAX * 256];  // A = [agg | x] split hi
__device__ __nv_bfloat16 g_Alo[(size_t)NMAX * 256];  // A split lo
__device__ float g_x1[(size_t)NMAX * DIM];           // layer-1 activations fp32 (agg2 input)
__device__ __nv_bfloat16 g_B1hi[32768], g_B1lo[32768];     // layer1 Wt [n=128][k=256]
__device__ __nv_bfloat16 g_B23hi[65536], g_B23lo[65536];   // layers2+3 Wt [n=256][k=256]
__device__ float g_b1[128];
__device__ float g_b23[256];
__device__ int   g_deg[NMAX];
__device__ int   g_rowptr[NMAX + 1];
__device__ int   g_cursor[NMAX];
__device__ int   g_col[EMAX];
__device__ int   g_bsum[SCAN_BLOCKS];
__device__ int   g_boff[SCAN_BLOCKS + 1];
__device__ int   g_is64;

// ---------------- edge-index dtype detection ----------------
__global__ void detect_kernel(const unsigned long long* ei) {
    int lane = threadIdx.x;
    unsigned long long hi = 0;
    #pragma unroll
    for (int k = 0; k < 4; k++) hi |= (ei[lane + 32 * k] >> 32);
    unsigned any = __ballot_sync(0xFFFFFFFFu, hi != 0ULL);
    if (lane == 0) g_is64 = (any == 0u);
}

__device__ __forceinline__ int edge_at(const void* ei, long long idx) {
    if (g_is64) return (int)((const long long*)ei)[idx];
    return ((const int*)ei)[idx];
}

// ---------------- CSR build ----------------
__global__ void zero_deg_kernel(int n) {
    int i = blockIdx.x * blockDim.x + threadIdx.x;
    if (i < n) g_deg[i] = 0;
}
__global__ void count_kernel(const void* ei, int e) {
    int i = blockIdx.x * blockDim.x + threadIdx.x;
    if (i >= e) return;
    atomicAdd(&g_deg[edge_at(ei, (long long)e + i)], 1);
}
__device__ __forceinline__ int warp_incl_scan(int v, int lane) {
    #pragma unroll
    for (int o = 1; o < 32; o <<= 1) {
        int t = __shfl_up_sync(0xFFFFFFFFu, v, o);
        if (lane >= o) v += t;
    }
    return v;
}
__device__ __forceinline__ int block_scan256(int v, int tid, int* block_total) {
    __shared__ int wsum[8];
    int lane = tid & 31, wid = tid >> 5;
    int incl = warp_incl_scan(v, lane);
    if (lane == 31) wsum[wid] = incl;
    __syncthreads();
    if (wid == 0) {
        int s = (lane < 8) ? wsum[lane] : 0;
        s = warp_incl_scan(s, lane);
        if (lane < 8) wsum[lane] = s;
    }
    __syncthreads();
    int off = (wid > 0) ? wsum[wid - 1] : 0;
    *block_total = wsum[7];
    return off + incl - v;
}
__global__ void scan1_kernel(int n) {
    int tid = threadIdx.x;
    int i = blockIdx.x * 256 + tid;
    int v = (i < n) ? g_deg[i] : 0;
    int total;
    int excl = block_scan256(v, tid, &total);
    if (i < n) g_rowptr[i] = excl;
    if (tid == 0) g_bsum[blockIdx.x] = total;
}
__global__ void scan2_kernel() {
    int tid = threadIdx.x;
    int v = (tid < SCAN_BLOCKS) ? g_bsum[tid] : 0;
    int total;
    int excl = block_scan256(v, tid, &total);
    if (tid < SCAN_BLOCKS) g_boff[tid] = excl;
    if (tid == 0) g_boff[SCAN_BLOCKS] = total;
}
__global__ void scan3_kernel(int n) {
    int i = blockIdx.x * blockDim.x + threadIdx.x;
    if (i < n) {
        int r = g_rowptr[i] + g_boff[i >> 8];
        g_rowptr[i] = r;
        g_cursor[i] = r;
    }
    if (i == 0) g_rowptr[n] = g_boff[SCAN_BLOCKS];
}
__global__ void scatter_kernel(const void* ei, int e) {
    int i = blockIdx.x * blockDim.x + threadIdx.x;
    if (i >= e) return;
    int src = edge_at(ei, i);
    int dst = edge_at(ei, (long long)e + i);
    g_col[atomicAdd(&g_cursor[dst], 1)] = src;
}

// ---------------- weight prep: Wt[n][k] row-major bf16 hi/lo ----------------
__global__ void prep_kernel(const float* __restrict__ W1l, const float* __restrict__ b1l,
                            const float* __restrict__ W1r,
                            const float* __restrict__ W2l, const float* __restrict__ b2l,
                            const float* __restrict__ W2r,
                            const float* __restrict__ W3l, const float* __restrict__ b3l,
                            const float* __restrict__ W3r) {
    int i = blockIdx.x * blockDim.x + threadIdx.x;
    if (i < 32768) {                       // layer-1: [n=128][k=256]
        int n = i >> 8, k = i & 255;
        float w = (k < 128) ? W1l[n * 128 + k] : W1r[n * 128 + (k - 128)];
        __nv_bfloat16 hi = __float2bfloat16(w);
        g_B1hi[i] = hi;
        g_B1lo[i] = __float2bfloat16(w - __bfloat162float(hi));
    } else if (i < 32768 + 65536) {        // layers-2+3: [n=256][k=256]
        int t = i - 32768;
        int n = t >> 8, k = t & 255;
        const float* W = (n < 128) ? ((k < 128) ? W2l : W2r)
                                   : ((k < 128) ? W3l : W3r);
        float w = W[(n & 127) * 128 + (k & 127)];
        __nv_bfloat16 hi = __float2bfloat16(w);
        g_B23hi[t] = hi;
        g_B23lo[t] = __float2bfloat16(w - __bfloat162float(hi));
    } else if (i < 98304 + 128) {
        int t = i - 98304;
        g_b1[t] = b1l[t];
    } else if (i < 98432 + 256) {
        int t = i - 98432;
        g_b23[t] = (t < 128) ? b2l[t] : b3l[t - 128];
    }
}

// ---------------- mean aggregation: warp per node -> bf16 hi/lo into A cols [0,128) ----------------
__global__ void agg_kernel(const float* __restrict__ X,
                           __nv_bfloat16* __restrict__ Ahi, __nv_bfloat16* __restrict__ Alo, int n) {
    int warp = (blockIdx.x * blockDim.x + threadIdx.x) >> 5;
    int lane = threadIdx.x & 31;
    if (warp >= n) return;
    int s = g_rowptr[warp], e2 = g_rowptr[warp + 1];
    float4 acc = make_float4(0.f, 0.f, 0.f, 0.f);
    int j = s;
    for (; j + 1 < e2; j += 2) {
        int c0 = g_col[j], c1 = g_col[j + 1];
        float4 v0 = *(const float4*)(X + (size_t)c0 * DIM + lane * 4);
        float4 v1 = *(const float4*)(X + (size_t)c1 * DIM + lane * 4);
        acc.x += v0.x + v1.x; acc.y += v0.y + v1.y;
        acc.z += v0.z + v1.z; acc.w += v0.w + v1.w;
    }
    if (j < e2) {
        int c0 = g_col[j];
        float4 v0 = *(const float4*)(X + (size_t)c0 * DIM + lane * 4);
        acc.x += v0.x; acc.y += v0.y; acc.z += v0.z; acc.w += v0.w;
    }
    int cnt = e2 - s;
    float inv = 1.0f / (float)(cnt > 0 ? cnt : 1);
    float v[4] = {acc.x * inv, acc.y * inv, acc.z * inv, acc.w * inv};
    unsigned short h[4], l[4];
#pragma unroll
    for (int t = 0; t < 4; t++) {
        __nv_bfloat16 hb = __float2bfloat16(v[t]);
        __nv_bfloat16 lb = __float2bfloat16(v[t] - __bfloat162float(hb));
        h[t] = __bfloat16_as_ushort(hb);
        l[t] = __bfloat16_as_ushort(lb);
    }
    size_t base = (size_t)warp * 256 + lane * 4;
    *(uint2*)(Ahi + base) = make_uint2((uint32_t)h[0] | ((uint32_t)h[1] << 16), (uint32_t)h[2] | ((uint32_t)h[3] << 16));
    *(uint2*)(Alo + base) = make_uint2((uint32_t)l[0] | ((uint32_t)l[1] << 16), (uint32_t)l[2] | ((uint32_t)l[3] << 16));
}

// ---------------- convert x -> bf16 hi/lo into A cols [128,256) ----------------
__global__ void convx_kernel(const float* __restrict__ X,
                             __nv_bfloat16* __restrict__ Ahi, __nv_bfloat16* __restrict__ Alo, int n) {
    int i = blockIdx.x * blockDim.x + threadIdx.x;
    int total = n * 32;
    if (i >= total) return;
    int row = i >> 5;
    int c4 = (i & 31) * 4;
    float4 v = *(const float4*)(X + (size_t)row * DIM + c4);
    float vv[4] = {v.x, v.y, v.z, v.w};
    unsigned short h[4], l[4];
#pragma unroll
    for (int t = 0; t < 4; t++) {
        __nv_bfloat16 hb = __float2bfloat16(vv[t]);
        __nv_bfloat16 lb = __float2bfloat16(vv[t] - __bfloat162float(hb));
        h[t] = __bfloat16_as_ushort(hb);
        l[t] = __bfloat16_as_ushort(lb);
    }
    size_t base = (size_t)row * 256 + 128 + c4;
    *(uint2*)(Ahi + base) = make_uint2((uint32_t)h[0] | ((uint32_t)h[1] << 16), (uint32_t)h[2] | ((uint32_t)h[3] << 16));
    *(uint2*)(Alo + base) = make_uint2((uint32_t)l[0] | ((uint32_t)l[1] << 16), (uint32_t)l[2] | ((uint32_t)l[3] << 16));
}

// ---------------- mma.sync GEMM helpers ----------------
__device__ __forceinline__ uint32_t smem_u32(const void* p) {
    uint32_t a;
    asm("{ .reg .u64 t; cvta.to.shared.u64 t, %1; cvt.u32.u64 %0, t; }" : "=r"(a) : "l"(p));
    return a;
}
__device__ __forceinline__ void ldm_x4(uint32_t* r, uint32_t addr) {
    asm volatile("ldmatrix.sync.aligned.m8n8.x4.shared.b16 {%0,%1,%2,%3}, [%4];"
                 : "=r"(r[0]), "=r"(r[1]), "=r"(r[2]), "=r"(r[3]) : "r"(addr));
}
__device__ __forceinline__ void mma_bf16(float* c, const uint32_t* a, uint32_t b0, uint32_t b1) {
    asm volatile("mma.sync.aligned.m16n8k16.row.col.f32.bf16.bf16.f32 "
                 "{%0,%1,%2,%3}, {%4,%5,%6,%7}, {%8,%9}, {%0,%1,%2,%3};"
                 : "+f"(c[0]), "+f"(c[1]), "+f"(c[2]), "+f"(c[3])
                 : "r"(a[0]), "r"(a[1]), "r"(a[2]), "r"(a[3]), "r"(b0), "r"(b1));
}

// SMEM layout: 4 tiles [128 rows][72 halves] (64 data + 8 pad), 18432 B each
#define S_AHI 0
#define S_ALO 18432
#define S_BHI 36864
#define S_BLO 55296
#define GEMM_SMEM 73728
#define LDK 72

// D[128x128] = [Ahi|Alo concat-K] x Bt, 3-pass bf16 split, K=256 in 4 chunks of 64
template <bool L1>
__global__ void __launch_bounds__(512, 1)
mma_gemm_kernel(const __nv_bfloat16* __restrict__ gAhi, const __nv_bfloat16* __restrict__ gAlo,
                const __nv_bfloat16* __restrict__ Bhi, const __nv_bfloat16* __restrict__ Blo,
                const float* __restrict__ bias,
                float* __restrict__ outA, float* __restrict__ outB,
                __nv_bfloat16* __restrict__ wAhi, __nv_bfloat16* __restrict__ wAlo,
                float* __restrict__ x1out, int M) {
    extern __shared__ char smem[];
    uint32_t sb = smem_u32(smem);
    const int tid = threadIdx.x;
    const int lane = tid & 31, wid = tid >> 5;
    const int wm = wid & 3, wn = wid >> 2;
    const int ntile = blockIdx.x;
    const int m0 = blockIdx.y * 128;

    const __nv_bfloat16* Bh = Bhi + (size_t)ntile * 128 * 256;
    const __nv_bfloat16* Bl = Blo + (size_t)ntile * 128 * 256;

    float acc[8][4];
#pragma unroll
    for (int t = 0; t < 8; t++)
#pragma unroll
        for (int j = 0; j < 4; j++) acc[t][j] = 0.f;

    // ldmatrix lane address components (halves)
    const int aRow = wm * 32 + (lane & 15);
    const int aK   = (lane >> 4) * 8;
    const int bRow = wn * 32 + ((lane >> 4) & 1) * 8 + (lane & 7);
    const int bK   = ((lane >> 3) & 1) * 8;

    for (int kc = 0; kc < 4; kc++) {
        const int k0 = kc * 64;
        __syncthreads();
        // load chunk: 2 uint4 per thread per array
#pragma unroll
        for (int u = 0; u < 2; u++) {
            int idx = tid + u * 512;          // 0..1023
            int row = idx >> 3;
            int c8 = (idx & 7) * 8;
            uint4 vah = make_uint4(0, 0, 0, 0), val = vah;
            if (m0 + row < M) {
                vah = *(const uint4*)(gAhi + (size_t)(m0 + row) * 256 + k0 + c8);
                val = *(const uint4*)(gAlo + (size_t)(m0 + row) * 256 + k0 + c8);
            }
            *(uint4*)(smem + S_AHI + (row * LDK + c8) * 2) = vah;
            *(uint4*)(smem + S_ALO + (row * LDK + c8) * 2) = val;
            uint4 vbh = *(const uint4*)(Bh + (size_t)row * 256 + k0 + c8);
            uint4 vbl = *(const uint4*)(Bl + (size_t)row * 256 + k0 + c8);
            *(uint4*)(smem + S_BHI + (row * LDK + c8) * 2) = vbh;
            *(uint4*)(smem + S_BLO + (row * LDK + c8) * 2) = vbl;
        }
        __syncthreads();

#pragma unroll
        for (int ks = 0; ks < 4; ks++) {
            const int k16 = ks * 16;
            uint32_t ah[2][4], al[2][4], bh[2][4], bl[2][4];
#pragma unroll
            for (int mi = 0; mi < 2; mi++) {
                uint32_t off = ((aRow + mi * 16) * LDK + k16 + aK) * 2;
                ldm_x4(ah[mi], sb + S_AHI + off);
                ldm_x4(al[mi], sb + S_ALO + off);
            }
#pragma unroll
            for (int pr = 0; pr < 2; pr++) {
                uint32_t off = ((bRow + pr * 16) * LDK + k16 + bK) * 2;
                ldm_x4(bh[pr], sb + S_BHI + off);
                ldm_x4(bl[pr], sb + S_BLO + off);
            }
#pragma unroll
            for (int mi = 0; mi < 2; mi++)
#pragma unroll
                for (int ni = 0; ni < 4; ni++) {
                    int pr = ni >> 1, wh = ni & 1;
                    float* c = acc[mi * 4 + ni];
                    mma_bf16(c, ah[mi], bh[pr][wh * 2], bh[pr][wh * 2 + 1]);
                    mma_bf16(c, al[mi], bh[pr][wh * 2], bh[pr][wh * 2 + 1]);
                    mma_bf16(c, ah[mi], bl[pr][wh * 2], bl[pr][wh * 2 + 1]);
                }
        }
    }

    // ---- epilogue ----
#pragma unroll
    for (int mi = 0; mi < 2; mi++)
#pragma unroll
        for (int ni = 0; ni < 4; ni++) {
            float* c = acc[mi * 4 + ni];
            int cl = wn * 32 + ni * 8 + (lane & 3) * 2;
            float b0 = bias[ntile * 128 + cl];
            float b1 = bias[ntile * 128 + cl + 1];
#pragma unroll
            for (int half = 0; half < 2; half++) {
                int gr = m0 + wm * 32 + mi * 16 + (lane >> 2) + half * 8;
                float v0 = c[half * 2] + b0;
                float v1 = c[half * 2 + 1] + b1;
                if (gr < M) {
                    if (L1) {
                        v0 = fmaxf(v0, 0.f);
                        v1 = fmaxf(v1, 0.f);
                        *(float2*)(x1out + (size_t)gr * 128 + cl) = make_float2(v0, v1);
                        __nv_bfloat16 h0 = __float2bfloat16(v0);
                        __nv_bfloat16 h1 = __float2bfloat16(v1);
                        unsigned short l0 = __bfloat16_as_ushort(__float2bfloat16(v0 - __bfloat162float(h0)));
                        unsigned short l1 = __bfloat16_as_ushort(__float2bfloat16(v1 - __bfloat162float(h1)));
                        *(uint32_t*)(wAhi + (size_t)gr * 256 + 128 + cl) =
                            (uint32_t)__bfloat16_as_ushort(h0) | ((uint32_t)__bfloat16_as_ushort(h1) << 16);
                        *(uint32_t*)(wAlo + (size_t)gr * 256 + 128 + cl) =
                            (uint32_t)l0 | ((uint32_t)l1 << 16);
                    } else {
                        float* dst = (ntile == 0 ? outA : outB);
                        *(float2*)(dst + (size_t)gr * 128 + cl) = make_float2(v0, v1);
                    }
                }
            }
        }
}

// ---------------- host launch ----------------
extern "C" void kernel_launch(void* const* d_in, const int* in_sizes, int n_in,
                              void* d_out, int out_size) {
    const float* x   = (const float*)d_in[0];
    const void*  ei  = d_in[1];
    const float* W1l = (const float*)d_in[2];
    const float* b1l = (const float*)d_in[3];
    const float* W1r = (const float*)d_in[4];
    const float* W2l = (const float*)d_in[5];
    const float* b2l = (const float*)d_in[6];
    const float* W2r = (const float*)d_in[7];
    const float* W3l = (const float*)d_in[8];
    const float* b3l = (const float*)d_in[9];
    const float* W3r = (const float*)d_in[10];

    int n = in_sizes[0] / DIM;   // 50000
    int e = in_sizes[1] / 2;     // 800000

    float* out0 = (float*)d_out;                     // h_ (layer 2)
    float* out1 = out0 + (size_t)n * DIM;            // h  (layer 3)

    __nv_bfloat16 *Ahi, *Alo, *B1hi, *B1lo, *B23hi, *B23lo;
    float *x1, *b1, *b23;
    cudaGetSymbolAddress((void**)&Ahi,   g_Ahi);
    cudaGetSymbolAddress((void**)&Alo,   g_Alo);
    cudaGetSymbolAddress((void**)&B1hi,  g_B1hi);
    cudaGetSymbolAddress((void**)&B1lo,  g_B1lo);
    cudaGetSymbolAddress((void**)&B23hi, g_B23hi);
    cudaGetSymbolAddress((void**)&B23lo, g_B23lo);
    cudaGetSymbolAddress((void**)&x1,    g_x1);
    cudaGetSymbolAddress((void**)&b1,    g_b1);
    cudaGetSymbolAddress((void**)&b23,   g_b23);

    cudaFuncSetAttribute(mma_gemm_kernel<true>,  cudaFuncAttributeMaxDynamicSharedMemorySize, GEMM_SMEM);
    cudaFuncSetAttribute(mma_gemm_kernel<false>, cudaFuncAttributeMaxDynamicSharedMemorySize, GEMM_SMEM);

    int eblocks = (e + 255) / 256;
    int nblocks = (n + 255) / 256;
    int mtiles = (n + 127) / 128;

    // CSR build
    detect_kernel<<<1, 32>>>((const unsigned long long*)ei);
    zero_deg_kernel<<<nblocks, 256>>>(n);
    count_kernel<<<eblocks, 256>>>(ei, e);
    scan1_kernel<<<SCAN_BLOCKS, 256>>>(n);
    scan2_kernel<<<1, 256>>>();
    scan3_kernel<<<nblocks, 256>>>(n);
    scatter_kernel<<<eblocks, 256>>>(ei, e);

    // Weight prep
    prep_kernel<<<(98688 + 255) / 256, 256>>>(W1l, b1l, W1r, W2l, b2l, W2r, W3l, b3l, W3r);

    // Layer 1: A = [mean-agg(x) | x]; x1 = relu(A @ W1t + b1); epilogue emits x1 fp32 + hi/lo
    agg_kernel<<<(n + 7) / 8, 256>>>(x, Ahi, Alo, n);
    convx_kernel<<<(n * 32 + 255) / 256, 256>>>(x, Ahi, Alo, n);
    mma_gemm_kernel<true><<<dim3(1, mtiles), 512, GEMM_SMEM>>>(
        Ahi, Alo, B1hi, B1lo, b1, nullptr, nullptr, Ahi, Alo, x1, n);

    // Layers 2+3: A = [mean-agg(x1) | x1]; [h_|h] = A @ W23t + b23
    agg_kernel<<<(n + 7) / 8, 256>>>(x1, Ahi, Alo, n);
    mma_gemm_kernel<false><<<dim3(2, mtiles), 512, GEMM_SMEM>>>(
        Ahi, Alo, B23hi, B23lo, b23, out0, out1, nullptr, nullptr, nullptr, n);
}